// round 1
// baseline (speedup 1.0000x reference)
#include <cuda_runtime.h>
#include <math.h>

#define EPS 1e-5f
#define SLOPE 0.01f

// Shapes
#define B_    64
#define CIN   3
#define HIN   224
#define C1    96
#define H1    56
#define HO    14
#define KK    16
#define COFF  32
#define COUT  768
#define KDIM  1536          // C1 * KK
#define NPIX  (B_*HO*HO)    // 12544

// Scratch (static device globals; allocation-free per harness rules)
__device__ float g_h[(size_t)B_*H1*H1*C1];        // NHWC: [b][y][x][c]  ~77MB
__device__ float g_off[(size_t)NPIX*COFF];        // [pix][32]          ~1.6MB
__device__ float g_S[(size_t)NPIX*KDIM];          // [pix][c*16+kk]     ~77MB

// ---------------------------------------------------------------------------
// Kernel 1: stem conv (4x4 stride 4, VALID) + BN1 + LeakyReLU -> g_h (NHWC)
// grid (56, 64), block 256
// ---------------------------------------------------------------------------
__global__ void stem_kernel(const float* __restrict__ x,
                            const float* __restrict__ w,
                            const float* __restrict__ bias,
                            const float* __restrict__ g,
                            const float* __restrict__ bb,
                            const float* __restrict__ bm,
                            const float* __restrict__ bv)
{
    __shared__ float xs[3*4*224];      // 2688 floats: input rows
    __shared__ float ws[48*96];        // 4608 floats, layout [k][c]
    __shared__ float sc_s[96], sh_s[96];

    const int oy = blockIdx.x;
    const int b  = blockIdx.y;
    const int tid = threadIdx.x;

    // load 4 input rows for all 3 channels
    for (int i = tid; i < 2688; i += 256) {
        int ic  = i / 896;
        int rem = i % 896;
        int r   = rem / 224;
        int col = rem % 224;
        xs[i] = x[(((size_t)b*CIN + ic)*HIN + (oy*4 + r))*HIN + col];
    }
    // weights transposed to [k48][c96]
    for (int i = tid; i < 4608; i += 256) {
        int c = i / 48;
        int k = i % 48;
        ws[k*96 + c] = w[i];
    }
    if (tid < 96) {
        float inv = g[tid] * rsqrtf(bv[tid] + EPS);
        sc_s[tid] = inv;
        sh_s[tid] = bb[tid] - bm[tid]*inv;
    }
    __syncthreads();

    // 56 ox * 96 c = 5376 outputs
    for (int i = tid; i < 56*96; i += 256) {
        int ox = i / 96;
        int c  = i % 96;
        float acc = bias[c];
#pragma unroll
        for (int ic = 0; ic < 3; ic++)
#pragma unroll
            for (int r = 0; r < 4; r++)
#pragma unroll
                for (int kx = 0; kx < 4; kx++)
                    acc += xs[ic*896 + r*224 + ox*4 + kx] *
                           ws[(ic*16 + r*4 + kx)*96 + c];
        float yv = acc*sc_s[c] + sh_s[c];
        yv = (yv >= 0.f) ? yv : SLOPE*yv;
        g_h[(((size_t)b*H1 + oy)*H1 + ox)*C1 + c] = yv;
    }
}

// ---------------------------------------------------------------------------
// Kernel 2: offset conv (4x4 stride 4) on h -> g_off [pix][32]
// grid 12544, block 256 (8 threads per output channel)
// ---------------------------------------------------------------------------
__global__ void offconv_kernel(const float* __restrict__ ow,
                               const float* __restrict__ ob)
{
    __shared__ float patch[KDIM];   // [p=ky*4+kx][c]
    const int pix = blockIdx.x;
    const int b   = pix / (HO*HO);
    const int hw  = pix % (HO*HO);
    const int oy  = hw / HO;
    const int ox  = hw % HO;
    const int tid = threadIdx.x;

    for (int i = tid; i < KDIM; i += 256) {
        int p = i / 96;
        int c = i % 96;
        int ky = p / 4, kx = p % 4;
        patch[i] = g_h[(((size_t)b*H1 + (oy*4+ky))*H1 + (ox*4+kx))*C1 + c];
    }
    __syncthreads();

    const int o    = tid >> 3;
    const int lane = tid & 7;
    float acc = 0.f;
    // off_w layout: [o][c][ky][kx] -> j = c*16 + k
    for (int j = lane; j < KDIM; j += 8) {
        int c = j >> 4;
        int k = j & 15;
        acc += patch[k*96 + c] * ow[(size_t)o*KDIM + j];
    }
    acc += __shfl_down_sync(0xffffffffu, acc, 4, 8);
    acc += __shfl_down_sync(0xffffffffu, acc, 2, 8);
    acc += __shfl_down_sync(0xffffffffu, acc, 1, 8);
    if (lane == 0)
        g_off[(size_t)pix*COFF + o] = acc + ob[o];
}

// ---------------------------------------------------------------------------
// Kernel 3: deformable bilinear sampling -> g_S [pix][c*16+kk]
// grid 12544, block 256
// ---------------------------------------------------------------------------
__global__ void sample_kernel()
{
    __shared__ int   y0s[KK], x0s[KK];
    __shared__ float wys[KK], wxs[KK];
    __shared__ float s_tile[KDIM];

    const int pix = blockIdx.x;
    const int b   = pix / (HO*HO);
    const int hw  = pix % (HO*HO);
    const int ho  = hw / HO;
    const int wo  = hw % HO;
    const int tid = threadIdx.x;

    if (tid < KK) {
        int kk = tid;
        float offy = g_off[(size_t)pix*COFF + kk*2 + 0];
        float offx = g_off[(size_t)pix*COFF + kk*2 + 1];
        float py = (float)(ho*4 + (kk >> 2)) + offy;
        float px = (float)(wo*4 + (kk & 3))  + offx;
        float y0 = floorf(py);
        float x0 = floorf(px);
        y0s[kk] = (int)y0;
        x0s[kk] = (int)x0;
        wys[kk] = py - y0;
        wxs[kk] = px - x0;
    }
    __syncthreads();

    for (int t = tid; t < KDIM; t += 256) {
        int c  = t % 96;           // consecutive threads -> consecutive c: coalesced gathers
        int kk = t / 96;
        int y0 = y0s[kk], x0 = x0s[kk];
        float fy = wys[kk], fx = wxs[kk];

        const size_t imgBase = (size_t)b*H1*H1*C1;
        float v00 = 0.f, v01 = 0.f, v10 = 0.f, v11 = 0.f;
        bool y0v = (y0   >= 0) & (y0   < H1);
        bool y1v = (y0+1 >= 0) & (y0+1 < H1);
        bool x0v = (x0   >= 0) & (x0   < H1);
        bool x1v = (x0+1 >= 0) & (x0+1 < H1);
        if (y0v & x0v) v00 = g_h[imgBase + ((size_t)y0*H1 + x0)*C1 + c];
        if (y0v & x1v) v01 = g_h[imgBase + ((size_t)y0*H1 + (x0+1))*C1 + c];
        if (y1v & x0v) v10 = g_h[imgBase + ((size_t)(y0+1)*H1 + x0)*C1 + c];
        if (y1v & x1v) v11 = g_h[imgBase + ((size_t)(y0+1)*H1 + (x0+1))*C1 + c];

        float s = v00*(1.f-fy)*(1.f-fx) + v01*(1.f-fy)*fx
                + v10*fy*(1.f-fx)       + v11*fy*fx;
        s_tile[c*KK + kk] = s;     // reorder to match dcn_w inner layout
    }
    __syncthreads();

    for (int t = tid; t < KDIM; t += 256)
        g_S[(size_t)pix*KDIM + t] = s_tile[t];
}

// ---------------------------------------------------------------------------
// Kernel 4: SGEMM  out[M=12544, N=768] = S[M,K=1536] * W[N,K]^T
// fused: + dcn_b, BN2, LeakyReLU. Output layout [b, hw, c] == row-major C.
// BM=BN=128, BK=16, 256 threads, 8x8 microtile.
// grid (6, 98)
// ---------------------------------------------------------------------------
#define BM 128
#define BN 128
#define BK 16
#define PAD 132

__global__ __launch_bounds__(256, 2)
void gemm_kernel(const float* __restrict__ Wd,
                 const float* __restrict__ dcn_b,
                 const float* __restrict__ g,
                 const float* __restrict__ bb,
                 const float* __restrict__ bm,
                 const float* __restrict__ bv,
                 float* __restrict__ out)
{
    __shared__ float As[BK][PAD];
    __shared__ float Bs[BK][PAD];

    const int tid   = threadIdx.x;
    const int mBase = blockIdx.y * BM;
    const int nBase = blockIdx.x * BN;
    const int tr = tid / 16;     // 0..15
    const int tc = tid % 16;     // 0..15

    const int lRow = tid / 4;        // 0..63
    const int lCol = (tid % 4) * 4;  // 0,4,8,12

    float acc[8][8];
#pragma unroll
    for (int i = 0; i < 8; i++)
#pragma unroll
        for (int j = 0; j < 8; j++) acc[i][j] = 0.f;

    const float* Sbase = g_S;

    for (int k0 = 0; k0 < KDIM; k0 += BK) {
        float4 a0 = *(const float4*)&Sbase[(size_t)(mBase + lRow     )*KDIM + k0 + lCol];
        float4 a1 = *(const float4*)&Sbase[(size_t)(mBase + lRow + 64)*KDIM + k0 + lCol];
        float4 b0 = *(const float4*)&Wd  [(size_t)(nBase + lRow     )*KDIM + k0 + lCol];
        float4 b1 = *(const float4*)&Wd  [(size_t)(nBase + lRow + 64)*KDIM + k0 + lCol];

        As[lCol+0][lRow] = a0.x; As[lCol+1][lRow] = a0.y;
        As[lCol+2][lRow] = a0.z; As[lCol+3][lRow] = a0.w;
        As[lCol+0][lRow+64] = a1.x; As[lCol+1][lRow+64] = a1.y;
        As[lCol+2][lRow+64] = a1.z; As[lCol+3][lRow+64] = a1.w;

        Bs[lCol+0][lRow] = b0.x; Bs[lCol+1][lRow] = b0.y;
        Bs[lCol+2][lRow] = b0.z; Bs[lCol+3][lRow] = b0.w;
        Bs[lCol+0][lRow+64] = b1.x; Bs[lCol+1][lRow+64] = b1.y;
        Bs[lCol+2][lRow+64] = b1.z; Bs[lCol+3][lRow+64] = b1.w;

        __syncthreads();

#pragma unroll
        for (int k = 0; k < BK; k++) {
            float rm[8], rn[8];
#pragma unroll
            for (int i = 0; i < 8; i++) rm[i] = As[k][tr*8 + i];
#pragma unroll
            for (int j = 0; j < 8; j++) rn[j] = Bs[k][tc*8 + j];
#pragma unroll
            for (int i = 0; i < 8; i++)
#pragma unroll
                for (int j = 0; j < 8; j++)
                    acc[i][j] = fmaf(rm[i], rn[j], acc[i][j]);
        }
        __syncthreads();
    }

    // epilogue: bias + BN2 + leaky relu, write [m][n] row-major
    float sc[8], sh[8], bs[8];
#pragma unroll
    for (int j = 0; j < 8; j++) {
        int n = nBase + tc*8 + j;
        float inv = g[n] * rsqrtf(bv[n] + EPS);
        sc[j] = inv;
        sh[j] = bb[n] - bm[n]*inv;
        bs[j] = dcn_b[n];
    }
#pragma unroll
    for (int i = 0; i < 8; i++) {
        int m = mBase + tr*8 + i;
        float4 o0, o1;
        float vj[8];
#pragma unroll
        for (int j = 0; j < 8; j++) {
            float val = (acc[i][j] + bs[j]) * sc[j] + sh[j];
            vj[j] = (val >= 0.f) ? val : SLOPE*val;
        }
        o0.x = vj[0]; o0.y = vj[1]; o0.z = vj[2]; o0.w = vj[3];
        o1.x = vj[4]; o1.y = vj[5]; o1.z = vj[6]; o1.w = vj[7];
        *(float4*)&out[(size_t)m*COUT + nBase + tc*8 + 0] = o0;
        *(float4*)&out[(size_t)m*COUT + nBase + tc*8 + 4] = o1;
    }
}

// ---------------------------------------------------------------------------
extern "C" void kernel_launch(void* const* d_in, const int* in_sizes, int n_in,
                              void* d_out, int out_size)
{
    const float* x      = (const float*)d_in[0];
    const float* stem_w = (const float*)d_in[1];
    const float* stem_b = (const float*)d_in[2];
    const float* bn1_g  = (const float*)d_in[3];
    const float* bn1_b  = (const float*)d_in[4];
    const float* bn1_m  = (const float*)d_in[5];
    const float* bn1_v  = (const float*)d_in[6];
    const float* off_w  = (const float*)d_in[7];
    const float* off_b  = (const float*)d_in[8];
    const float* dcn_w  = (const float*)d_in[9];
    const float* dcn_b  = (const float*)d_in[10];
    const float* bn2_g  = (const float*)d_in[11];
    const float* bn2_b  = (const float*)d_in[12];
    const float* bn2_m  = (const float*)d_in[13];
    const float* bn2_v  = (const float*)d_in[14];
    float* out = (float*)d_out;

    stem_kernel<<<dim3(H1, B_), 256>>>(x, stem_w, stem_b,
                                       bn1_g, bn1_b, bn1_m, bn1_v);
    offconv_kernel<<<NPIX, 256>>>(off_w, off_b);
    sample_kernel<<<NPIX, 256>>>();
    gemm_kernel<<<dim3(COUT/BN, NPIX/BM), 256>>>(dcn_w, dcn_b,
                                                 bn2_g, bn2_b, bn2_m, bn2_v,
                                                 out);
}

// round 2
// speedup vs baseline: 1.0013x; 1.0013x over previous
#include <cuda_runtime.h>
#include <math.h>

#define EPS 1e-5f
#define SLOPE 0.01f

// Shapes
#define B_    64
#define CIN   3
#define HIN   224
#define C1    96
#define H1    56
#define HO    14
#define KK    16
#define COFF  32
#define COUT  768
#define KDIM  1536          // C1 * KK
#define NPIX  (B_*HO*HO)    // 12544

// Scratch (static device globals; allocation-free per harness rules)
__device__ float g_h[(size_t)B_*H1*H1*C1];        // NHWC: [b][y][x][c]  ~77MB
__device__ float g_off[(size_t)NPIX*COFF];        // [pix][32]          ~1.6MB
__device__ float g_S[(size_t)NPIX*KDIM];          // [pix][c*16+kk]     ~77MB

// ---------------------------------------------------------------------------
// Kernel 1: stem conv (4x4 stride 4, VALID) + BN1 + LeakyReLU -> g_h (NHWC)
// grid (56, 64), block 256
// ---------------------------------------------------------------------------
__global__ void stem_kernel(const float* __restrict__ x,
                            const float* __restrict__ w,
                            const float* __restrict__ bias,
                            const float* __restrict__ g,
                            const float* __restrict__ bb,
                            const float* __restrict__ bm,
                            const float* __restrict__ bv)
{
    __shared__ float xs[3*4*224];      // 2688 floats: input rows
    __shared__ float ws[48*96];        // 4608 floats, layout [k][c]
    __shared__ float sc_s[96], sh_s[96];

    const int oy = blockIdx.x;
    const int b  = blockIdx.y;
    const int tid = threadIdx.x;

    // load 4 input rows for all 3 channels
    for (int i = tid; i < 2688; i += 256) {
        int ic  = i / 896;
        int rem = i % 896;
        int r   = rem / 224;
        int col = rem % 224;
        xs[i] = x[(((size_t)b*CIN + ic)*HIN + (oy*4 + r))*HIN + col];
    }
    // weights transposed to [k48][c96]
    for (int i = tid; i < 4608; i += 256) {
        int c = i / 48;
        int k = i % 48;
        ws[k*96 + c] = w[i];
    }
    if (tid < 96) {
        float inv = g[tid] * rsqrtf(bv[tid] + EPS);
        sc_s[tid] = inv;
        sh_s[tid] = bb[tid] - bm[tid]*inv;
    }
    __syncthreads();

    // 56 ox * 96 c = 5376 outputs
    for (int i = tid; i < 56*96; i += 256) {
        int ox = i / 96;
        int c  = i % 96;
        float acc = bias[c];
#pragma unroll
        for (int ic = 0; ic < 3; ic++)
#pragma unroll
            for (int r = 0; r < 4; r++)
#pragma unroll
                for (int kx = 0; kx < 4; kx++)
                    acc += xs[ic*896 + r*224 + ox*4 + kx] *
                           ws[(ic*16 + r*4 + kx)*96 + c];
        float yv = acc*sc_s[c] + sh_s[c];
        yv = (yv >= 0.f) ? yv : SLOPE*yv;
        g_h[(((size_t)b*H1 + oy)*H1 + ox)*C1 + c] = yv;
    }
}

// ---------------------------------------------------------------------------
// Kernel 2: offset conv (4x4 stride 4) on h -> g_off [pix][32]
// grid 12544, block 256 (8 threads per output channel)
// ---------------------------------------------------------------------------
__global__ void offconv_kernel(const float* __restrict__ ow,
                               const float* __restrict__ ob)
{
    __shared__ float patch[KDIM];   // [p=ky*4+kx][c]
    const int pix = blockIdx.x;
    const int b   = pix / (HO*HO);
    const int hw  = pix % (HO*HO);
    const int oy  = hw / HO;
    const int ox  = hw % HO;
    const int tid = threadIdx.x;

    for (int i = tid; i < KDIM; i += 256) {
        int p = i / 96;
        int c = i % 96;
        int ky = p / 4, kx = p % 4;
        patch[i] = g_h[(((size_t)b*H1 + (oy*4+ky))*H1 + (ox*4+kx))*C1 + c];
    }
    __syncthreads();

    const int o    = tid >> 3;
    const int lane = tid & 7;
    float acc = 0.f;
    // off_w layout: [o][c][ky][kx] -> j = c*16 + k
    for (int j = lane; j < KDIM; j += 8) {
        int c = j >> 4;
        int k = j & 15;
        acc += patch[k*96 + c] * ow[(size_t)o*KDIM + j];
    }
    acc += __shfl_down_sync(0xffffffffu, acc, 4, 8);
    acc += __shfl_down_sync(0xffffffffu, acc, 2, 8);
    acc += __shfl_down_sync(0xffffffffu, acc, 1, 8);
    if (lane == 0)
        g_off[(size_t)pix*COFF + o] = acc + ob[o];
}

// ---------------------------------------------------------------------------
// Kernel 3: deformable bilinear sampling -> g_S [pix][c*16+kk]
// grid 12544, block 256
// ---------------------------------------------------------------------------
__global__ void sample_kernel()
{
    __shared__ int   y0s[KK], x0s[KK];
    __shared__ float wys[KK], wxs[KK];
    __shared__ float s_tile[KDIM];

    const int pix = blockIdx.x;
    const int b   = pix / (HO*HO);
    const int hw  = pix % (HO*HO);
    const int ho  = hw / HO;
    const int wo  = hw % HO;
    const int tid = threadIdx.x;

    if (tid < KK) {
        int kk = tid;
        float offy = g_off[(size_t)pix*COFF + kk*2 + 0];
        float offx = g_off[(size_t)pix*COFF + kk*2 + 1];
        float py = (float)(ho*4 + (kk >> 2)) + offy;
        float px = (float)(wo*4 + (kk & 3))  + offx;
        float y0 = floorf(py);
        float x0 = floorf(px);
        y0s[kk] = (int)y0;
        x0s[kk] = (int)x0;
        wys[kk] = py - y0;
        wxs[kk] = px - x0;
    }
    __syncthreads();

    for (int t = tid; t < KDIM; t += 256) {
        int c  = t % 96;           // consecutive threads -> consecutive c: coalesced gathers
        int kk = t / 96;
        int y0 = y0s[kk], x0 = x0s[kk];
        float fy = wys[kk], fx = wxs[kk];

        const size_t imgBase = (size_t)b*H1*H1*C1;
        float v00 = 0.f, v01 = 0.f, v10 = 0.f, v11 = 0.f;
        bool y0v = (y0   >= 0) & (y0   < H1);
        bool y1v = (y0+1 >= 0) & (y0+1 < H1);
        bool x0v = (x0   >= 0) & (x0   < H1);
        bool x1v = (x0+1 >= 0) & (x0+1 < H1);
        if (y0v & x0v) v00 = g_h[imgBase + ((size_t)y0*H1 + x0)*C1 + c];
        if (y0v & x1v) v01 = g_h[imgBase + ((size_t)y0*H1 + (x0+1))*C1 + c];
        if (y1v & x0v) v10 = g_h[imgBase + ((size_t)(y0+1)*H1 + x0)*C1 + c];
        if (y1v & x1v) v11 = g_h[imgBase + ((size_t)(y0+1)*H1 + (x0+1))*C1 + c];

        float s = v00*(1.f-fy)*(1.f-fx) + v01*(1.f-fy)*fx
                + v10*fy*(1.f-fx)       + v11*fy*fx;
        s_tile[c*KK + kk] = s;     // reorder to match dcn_w inner layout
    }
    __syncthreads();

    for (int t = tid; t < KDIM; t += 256)
        g_S[(size_t)pix*KDIM + t] = s_tile[t];
}

// ---------------------------------------------------------------------------
// Kernel 4: SGEMM  out[M=12544, N=768] = S[M,K=1536] * W[N,K]^T
// fused: + dcn_b, BN2, LeakyReLU. Output layout [b, hw, c] == row-major C.
// BM=BN=128, BK=16, 256 threads, 8x8 microtile.
// grid (6, 98)
// ---------------------------------------------------------------------------
#define BM 128
#define BN 128
#define BK 16
#define PAD 132

__global__ __launch_bounds__(256, 2)
void gemm_kernel(const float* __restrict__ Wd,
                 const float* __restrict__ dcn_b,
                 const float* __restrict__ g,
                 const float* __restrict__ bb,
                 const float* __restrict__ bm,
                 const float* __restrict__ bv,
                 float* __restrict__ out)
{
    __shared__ float As[BK][PAD];
    __shared__ float Bs[BK][PAD];

    const int tid   = threadIdx.x;
    const int mBase = blockIdx.y * BM;
    const int nBase = blockIdx.x * BN;
    const int tr = tid / 16;     // 0..15
    const int tc = tid % 16;     // 0..15

    const int lRow = tid / 4;        // 0..63
    const int lCol = (tid % 4) * 4;  // 0,4,8,12

    float acc[8][8];
#pragma unroll
    for (int i = 0; i < 8; i++)
#pragma unroll
        for (int j = 0; j < 8; j++) acc[i][j] = 0.f;

    const float* Sbase = g_S;

    for (int k0 = 0; k0 < KDIM; k0 += BK) {
        float4 a0 = *(const float4*)&Sbase[(size_t)(mBase + lRow     )*KDIM + k0 + lCol];
        float4 a1 = *(const float4*)&Sbase[(size_t)(mBase + lRow + 64)*KDIM + k0 + lCol];
        float4 b0 = *(const float4*)&Wd  [(size_t)(nBase + lRow     )*KDIM + k0 + lCol];
        float4 b1 = *(const float4*)&Wd  [(size_t)(nBase + lRow + 64)*KDIM + k0 + lCol];

        As[lCol+0][lRow] = a0.x; As[lCol+1][lRow] = a0.y;
        As[lCol+2][lRow] = a0.z; As[lCol+3][lRow] = a0.w;
        As[lCol+0][lRow+64] = a1.x; As[lCol+1][lRow+64] = a1.y;
        As[lCol+2][lRow+64] = a1.z; As[lCol+3][lRow+64] = a1.w;

        Bs[lCol+0][lRow] = b0.x; Bs[lCol+1][lRow] = b0.y;
        Bs[lCol+2][lRow] = b0.z; Bs[lCol+3][lRow] = b0.w;
        Bs[lCol+0][lRow+64] = b1.x; Bs[lCol+1][lRow+64] = b1.y;
        Bs[lCol+2][lRow+64] = b1.z; Bs[lCol+3][lRow+64] = b1.w;

        __syncthreads();

#pragma unroll
        for (int k = 0; k < BK; k++) {
            float rm[8], rn[8];
#pragma unroll
            for (int i = 0; i < 8; i++) rm[i] = As[k][tr*8 + i];
#pragma unroll
            for (int j = 0; j < 8; j++) rn[j] = Bs[k][tc*8 + j];
#pragma unroll
            for (int i = 0; i < 8; i++)
#pragma unroll
                for (int j = 0; j < 8; j++)
                    acc[i][j] = fmaf(rm[i], rn[j], acc[i][j]);
        }
        __syncthreads();
    }

    // epilogue: bias + BN2 + leaky relu, write [m][n] row-major
    float sc[8], sh[8], bs[8];
#pragma unroll
    for (int j = 0; j < 8; j++) {
        int n = nBase + tc*8 + j;
        float inv = g[n] * rsqrtf(bv[n] + EPS);
        sc[j] = inv;
        sh[j] = bb[n] - bm[n]*inv;
        bs[j] = dcn_b[n];
    }
#pragma unroll
    for (int i = 0; i < 8; i++) {
        int m = mBase + tr*8 + i;
        float4 o0, o1;
        float vj[8];
#pragma unroll
        for (int j = 0; j < 8; j++) {
            float val = (acc[i][j] + bs[j]) * sc[j] + sh[j];
            vj[j] = (val >= 0.f) ? val : SLOPE*val;
        }
        o0.x = vj[0]; o0.y = vj[1]; o0.z = vj[2]; o0.w = vj[3];
        o1.x = vj[4]; o1.y = vj[5]; o1.z = vj[6]; o1.w = vj[7];
        *(float4*)&out[(size_t)m*COUT + nBase + tc*8 + 0] = o0;
        *(float4*)&out[(size_t)m*COUT + nBase + tc*8 + 4] = o1;
    }
}

// ---------------------------------------------------------------------------
extern "C" void kernel_launch(void* const* d_in, const int* in_sizes, int n_in,
                              void* d_out, int out_size)
{
    const float* x      = (const float*)d_in[0];
    const float* stem_w = (const float*)d_in[1];
    const float* stem_b = (const float*)d_in[2];
    const float* bn1_g  = (const float*)d_in[3];
    const float* bn1_b  = (const float*)d_in[4];
    const float* bn1_m  = (const float*)d_in[5];
    const float* bn1_v  = (const float*)d_in[6];
    const float* off_w  = (const float*)d_in[7];
    const float* off_b  = (const float*)d_in[8];
    const float* dcn_w  = (const float*)d_in[9];
    const float* dcn_b  = (const float*)d_in[10];
    const float* bn2_g  = (const float*)d_in[11];
    const float* bn2_b  = (const float*)d_in[12];
    const float* bn2_m  = (const float*)d_in[13];
    const float* bn2_v  = (const float*)d_in[14];
    float* out = (float*)d_out;

    stem_kernel<<<dim3(H1, B_), 256>>>(x, stem_w, stem_b,
                                       bn1_g, bn1_b, bn1_m, bn1_v);
    offconv_kernel<<<NPIX, 256>>>(off_w, off_b);
    sample_kernel<<<NPIX, 256>>>();
    gemm_kernel<<<dim3(COUT/BN, NPIX/BM), 256>>>(dcn_w, dcn_b,
                                                 bn2_g, bn2_b, bn2_m, bn2_v,
                                                 out);
}

// round 3
// speedup vs baseline: 1.0022x; 1.0010x over previous
#include <cuda_runtime.h>
#include <math.h>

#define EPS 1e-5f
#define SLOPE 0.01f

// Shapes
#define B_    64
#define CIN   3
#define HIN   224
#define C1    96
#define H1    56
#define HO    14
#define KK    16
#define COFF  32
#define COUT  768
#define KDIM  1536          // C1 * KK
#define NPIX  (B_*HO*HO)    // 12544

// Scratch (static device globals; allocation-free per harness rules)
__device__ float g_h[(size_t)B_*H1*H1*C1];        // NHWC: [b][y][x][c]  ~77MB
__device__ float g_off[(size_t)NPIX*COFF];        // [pix][32]          ~1.6MB
__device__ float g_S[(size_t)NPIX*KDIM];          // [pix][c*16+kk]     ~77MB

// ---------------------------------------------------------------------------
// Kernel 1: stem conv (4x4 stride 4, VALID) + BN1 + LeakyReLU -> g_h (NHWC)
// grid (56, 64), block 256
// ---------------------------------------------------------------------------
__global__ void stem_kernel(const float* __restrict__ x,
                            const float* __restrict__ w,
                            const float* __restrict__ bias,
                            const float* __restrict__ g,
                            const float* __restrict__ bb,
                            const float* __restrict__ bm,
                            const float* __restrict__ bv)
{
    __shared__ float xs[3*4*224];      // 2688 floats: input rows
    __shared__ float ws[48*96];        // 4608 floats, layout [k][c]
    __shared__ float sc_s[96], sh_s[96];

    const int oy = blockIdx.x;
    const int b  = blockIdx.y;
    const int tid = threadIdx.x;

    // load 4 input rows for all 3 channels
    for (int i = tid; i < 2688; i += 256) {
        int ic  = i / 896;
        int rem = i % 896;
        int r   = rem / 224;
        int col = rem % 224;
        xs[i] = x[(((size_t)b*CIN + ic)*HIN + (oy*4 + r))*HIN + col];
    }
    // weights transposed to [k48][c96]
    for (int i = tid; i < 4608; i += 256) {
        int c = i / 48;
        int k = i % 48;
        ws[k*96 + c] = w[i];
    }
    if (tid < 96) {
        float inv = g[tid] * rsqrtf(bv[tid] + EPS);
        sc_s[tid] = inv;
        sh_s[tid] = bb[tid] - bm[tid]*inv;
    }
    __syncthreads();

    // 56 ox * 96 c = 5376 outputs
    for (int i = tid; i < 56*96; i += 256) {
        int ox = i / 96;
        int c  = i % 96;
        float acc = bias[c];
#pragma unroll
        for (int ic = 0; ic < 3; ic++)
#pragma unroll
            for (int r = 0; r < 4; r++)
#pragma unroll
                for (int kx = 0; kx < 4; kx++)
                    acc += xs[ic*896 + r*224 + ox*4 + kx] *
                           ws[(ic*16 + r*4 + kx)*96 + c];
        float yv = acc*sc_s[c] + sh_s[c];
        yv = (yv >= 0.f) ? yv : SLOPE*yv;
        g_h[(((size_t)b*H1 + oy)*H1 + ox)*C1 + c] = yv;
    }
}

// ---------------------------------------------------------------------------
// Kernel 2: offset conv (4x4 stride 4) on h -> g_off [pix][32]
// grid 12544, block 256 (8 threads per output channel)
// ---------------------------------------------------------------------------
__global__ void offconv_kernel(const float* __restrict__ ow,
                               const float* __restrict__ ob)
{
    __shared__ float patch[KDIM];   // [p=ky*4+kx][c]
    const int pix = blockIdx.x;
    const int b   = pix / (HO*HO);
    const int hw  = pix % (HO*HO);
    const int oy  = hw / HO;
    const int ox  = hw % HO;
    const int tid = threadIdx.x;

    for (int i = tid; i < KDIM; i += 256) {
        int p = i / 96;
        int c = i % 96;
        int ky = p / 4, kx = p % 4;
        patch[i] = g_h[(((size_t)b*H1 + (oy*4+ky))*H1 + (ox*4+kx))*C1 + c];
    }
    __syncthreads();

    const int o    = tid >> 3;
    const int lane = tid & 7;
    float acc = 0.f;
    // off_w layout: [o][c][ky][kx] -> j = c*16 + k
    for (int j = lane; j < KDIM; j += 8) {
        int c = j >> 4;
        int k = j & 15;
        acc += patch[k*96 + c] * ow[(size_t)o*KDIM + j];
    }
    acc += __shfl_down_sync(0xffffffffu, acc, 4, 8);
    acc += __shfl_down_sync(0xffffffffu, acc, 2, 8);
    acc += __shfl_down_sync(0xffffffffu, acc, 1, 8);
    if (lane == 0)
        g_off[(size_t)pix*COFF + o] = acc + ob[o];
}

// ---------------------------------------------------------------------------
// Kernel 3: deformable bilinear sampling -> g_S [pix][c*16+kk]
// grid 12544, block 256
// ---------------------------------------------------------------------------
__global__ void sample_kernel()
{
    __shared__ int   y0s[KK], x0s[KK];
    __shared__ float wys[KK], wxs[KK];
    __shared__ float s_tile[KDIM];

    const int pix = blockIdx.x;
    const int b   = pix / (HO*HO);
    const int hw  = pix % (HO*HO);
    const int ho  = hw / HO;
    const int wo  = hw % HO;
    const int tid = threadIdx.x;

    if (tid < KK) {
        int kk = tid;
        float offy = g_off[(size_t)pix*COFF + kk*2 + 0];
        float offx = g_off[(size_t)pix*COFF + kk*2 + 1];
        float py = (float)(ho*4 + (kk >> 2)) + offy;
        float px = (float)(wo*4 + (kk & 3))  + offx;
        float y0 = floorf(py);
        float x0 = floorf(px);
        y0s[kk] = (int)y0;
        x0s[kk] = (int)x0;
        wys[kk] = py - y0;
        wxs[kk] = px - x0;
    }
    __syncthreads();

    for (int t = tid; t < KDIM; t += 256) {
        int c  = t % 96;           // consecutive threads -> consecutive c: coalesced gathers
        int kk = t / 96;
        int y0 = y0s[kk], x0 = x0s[kk];
        float fy = wys[kk], fx = wxs[kk];

        const size_t imgBase = (size_t)b*H1*H1*C1;
        float v00 = 0.f, v01 = 0.f, v10 = 0.f, v11 = 0.f;
        bool y0v = (y0   >= 0) & (y0   < H1);
        bool y1v = (y0+1 >= 0) & (y0+1 < H1);
        bool x0v = (x0   >= 0) & (x0   < H1);
        bool x1v = (x0+1 >= 0) & (x0+1 < H1);
        if (y0v & x0v) v00 = g_h[imgBase + ((size_t)y0*H1 + x0)*C1 + c];
        if (y0v & x1v) v01 = g_h[imgBase + ((size_t)y0*H1 + (x0+1))*C1 + c];
        if (y1v & x0v) v10 = g_h[imgBase + ((size_t)(y0+1)*H1 + x0)*C1 + c];
        if (y1v & x1v) v11 = g_h[imgBase + ((size_t)(y0+1)*H1 + (x0+1))*C1 + c];

        float s = v00*(1.f-fy)*(1.f-fx) + v01*(1.f-fy)*fx
                + v10*fy*(1.f-fx)       + v11*fy*fx;
        s_tile[c*KK + kk] = s;     // reorder to match dcn_w inner layout
    }
    __syncthreads();

    for (int t = tid; t < KDIM; t += 256)
        g_S[(size_t)pix*KDIM + t] = s_tile[t];
}

// ---------------------------------------------------------------------------
// Kernel 4: SGEMM  out[M=12544, N=768] = S[M,K=1536] * W[N,K]^T
// fused: + dcn_b, BN2, LeakyReLU. Output layout [b, hw, c] == row-major C.
// BM=BN=128, BK=16, 256 threads, 8x8 microtile.
// grid (6, 98)
// ---------------------------------------------------------------------------
#define BM 128
#define BN 128
#define BK 16
#define PAD 132

__global__ __launch_bounds__(256, 2)
void gemm_kernel(const float* __restrict__ Wd,
                 const float* __restrict__ dcn_b,
                 const float* __restrict__ g,
                 const float* __restrict__ bb,
                 const float* __restrict__ bm,
                 const float* __restrict__ bv,
                 float* __restrict__ out)
{
    __shared__ float As[BK][PAD];
    __shared__ float Bs[BK][PAD];

    const int tid   = threadIdx.x;
    const int mBase = blockIdx.y * BM;
    const int nBase = blockIdx.x * BN;
    const int tr = tid / 16;     // 0..15
    const int tc = tid % 16;     // 0..15

    const int lRow = tid / 4;        // 0..63
    const int lCol = (tid % 4) * 4;  // 0,4,8,12

    float acc[8][8];
#pragma unroll
    for (int i = 0; i < 8; i++)
#pragma unroll
        for (int j = 0; j < 8; j++) acc[i][j] = 0.f;

    const float* Sbase = g_S;

    for (int k0 = 0; k0 < KDIM; k0 += BK) {
        float4 a0 = *(const float4*)&Sbase[(size_t)(mBase + lRow     )*KDIM + k0 + lCol];
        float4 a1 = *(const float4*)&Sbase[(size_t)(mBase + lRow + 64)*KDIM + k0 + lCol];
        float4 b0 = *(const float4*)&Wd  [(size_t)(nBase + lRow     )*KDIM + k0 + lCol];
        float4 b1 = *(const float4*)&Wd  [(size_t)(nBase + lRow + 64)*KDIM + k0 + lCol];

        As[lCol+0][lRow] = a0.x; As[lCol+1][lRow] = a0.y;
        As[lCol+2][lRow] = a0.z; As[lCol+3][lRow] = a0.w;
        As[lCol+0][lRow+64] = a1.x; As[lCol+1][lRow+64] = a1.y;
        As[lCol+2][lRow+64] = a1.z; As[lCol+3][lRow+64] = a1.w;

        Bs[lCol+0][lRow] = b0.x; Bs[lCol+1][lRow] = b0.y;
        Bs[lCol+2][lRow] = b0.z; Bs[lCol+3][lRow] = b0.w;
        Bs[lCol+0][lRow+64] = b1.x; Bs[lCol+1][lRow+64] = b1.y;
        Bs[lCol+2][lRow+64] = b1.z; Bs[lCol+3][lRow+64] = b1.w;

        __syncthreads();

#pragma unroll
        for (int k = 0; k < BK; k++) {
            float rm[8], rn[8];
#pragma unroll
            for (int i = 0; i < 8; i++) rm[i] = As[k][tr*8 + i];
#pragma unroll
            for (int j = 0; j < 8; j++) rn[j] = Bs[k][tc*8 + j];
#pragma unroll
            for (int i = 0; i < 8; i++)
#pragma unroll
                for (int j = 0; j < 8; j++)
                    acc[i][j] = fmaf(rm[i], rn[j], acc[i][j]);
        }
        __syncthreads();
    }

    // epilogue: bias + BN2 + leaky relu, write [m][n] row-major
    float sc[8], sh[8], bs[8];
#pragma unroll
    for (int j = 0; j < 8; j++) {
        int n = nBase + tc*8 + j;
        float inv = g[n] * rsqrtf(bv[n] + EPS);
        sc[j] = inv;
        sh[j] = bb[n] - bm[n]*inv;
        bs[j] = dcn_b[n];
    }
#pragma unroll
    for (int i = 0; i < 8; i++) {
        int m = mBase + tr*8 + i;
        float4 o0, o1;
        float vj[8];
#pragma unroll
        for (int j = 0; j < 8; j++) {
            float val = (acc[i][j] + bs[j]) * sc[j] + sh[j];
            vj[j] = (val >= 0.f) ? val : SLOPE*val;
        }
        o0.x = vj[0]; o0.y = vj[1]; o0.z = vj[2]; o0.w = vj[3];
        o1.x = vj[4]; o1.y = vj[5]; o1.z = vj[6]; o1.w = vj[7];
        *(float4*)&out[(size_t)m*COUT + nBase + tc*8 + 0] = o0;
        *(float4*)&out[(size_t)m*COUT + nBase + tc*8 + 4] = o1;
    }
}

// ---------------------------------------------------------------------------
extern "C" void kernel_launch(void* const* d_in, const int* in_sizes, int n_in,
                              void* d_out, int out_size)
{
    const float* x      = (const float*)d_in[0];
    const float* stem_w = (const float*)d_in[1];
    const float* stem_b = (const float*)d_in[2];
    const float* bn1_g  = (const float*)d_in[3];
    const float* bn1_b  = (const float*)d_in[4];
    const float* bn1_m  = (const float*)d_in[5];
    const float* bn1_v  = (const float*)d_in[6];
    const float* off_w  = (const float*)d_in[7];
    const float* off_b  = (const float*)d_in[8];
    const float* dcn_w  = (const float*)d_in[9];
    const float* dcn_b  = (const float*)d_in[10];
    const float* bn2_g  = (const float*)d_in[11];
    const float* bn2_b  = (const float*)d_in[12];
    const float* bn2_m  = (const float*)d_in[13];
    const float* bn2_v  = (const float*)d_in[14];
    float* out = (float*)d_out;

    stem_kernel<<<dim3(H1, B_), 256>>>(x, stem_w, stem_b,
                                       bn1_g, bn1_b, bn1_m, bn1_v);
    offconv_kernel<<<NPIX, 256>>>(off_w, off_b);
    sample_kernel<<<NPIX, 256>>>();
    gemm_kernel<<<dim3(COUT/BN, NPIX/BM), 256>>>(dcn_w, dcn_b,
                                                 bn2_g, bn2_b, bn2_m, bn2_v,
                                                 out);
}